// round 13
// baseline (speedup 1.0000x reference)
#include <cuda_runtime.h>
#include <math.h>

// ---------------------------------------------------------------------------
// ConnectedFilterLayerWithImplicitJacobian
//   filtered = residues * sigmoid(attrs2d @ w + b)
//   pack[tpre[i]]  = {+f, i};  pack[tpost[i]] = {-f, -1}   (permutation;
//   aligned leaves -> single 16B store)
//   scan pack.x with decoupled lookback (245 tiles: all SMs active);
//   at tpre slots scatter final prefix straight into y_node[node].
//   out[p] = y_node[node_of_pixel[p]]  (persistent grid, L1tex wf floor)
// ---------------------------------------------------------------------------

#define TMAX     (1 << 20)          // 2N = 1,000,000 <= 1,048,576
#define NMAX     (1 << 19)          // N = 500,000 <= 524,288
#define STILE    4096
#define STHREADS 512
#define SIPT     (STILE / STHREADS) // 8 packed elems per thread

__device__ float2 g_pack[TMAX];     // .x = delta value, .y = node id bits
__device__ float  g_ynode[NMAX];
// [0] = ticket counter, [1..] = lookback descriptors (flag<<32 | float bits)
__device__ unsigned long long g_scan_state[512];

#define FLAG_AGG 1u
#define FLAG_PRE 2u

__device__ __forceinline__ unsigned long long pack_desc(float v, unsigned f) {
    return ((unsigned long long)f << 32) | (unsigned long long)__float_as_uint(v);
}

// --------------- kernel 1: filtered + packed scatter (+ state reset) -------
__global__ void k_filtered(const float* __restrict__ weight,
                           const float* __restrict__ bias,
                           const float* __restrict__ residues,
                           const float* __restrict__ attrs,
                           const int*   __restrict__ tpre,
                           const int*   __restrict__ tpost,
                           int n, int nstate)
{
    if (blockIdx.x == 0 && threadIdx.x < nstate)
        g_scan_state[threadIdx.x] = 0ull;

    int i = blockIdx.x * blockDim.x + threadIdx.x;
    if (i >= n) return;

    int pr = tpre[i];
    int po = tpost[i];

    const float4* a = reinterpret_cast<const float4*>(attrs + (size_t)i * 8);
    float4 a0 = a[0];
    float4 a1 = a[1];
    float4 w0 = *reinterpret_cast<const float4*>(weight);
    float4 w1 = *(reinterpret_cast<const float4*>(weight) + 1);

    float logit = a0.x * w0.x + a0.y * w0.y + a0.z * w0.z + a0.w * w0.w
                + a1.x * w1.x + a1.y * w1.y + a1.z * w1.z + a1.w * w1.w
                + bias[0];
    float s = 1.0f / (1.0f + __expf(-logit));
    float f = residues[i] * s;

    // Leaf with aligned tpre: the two 8B entries are one aligned 16B slot.
    if (po == pr + 1 && (pr & 1) == 0) {
        float4 v;
        v.x = f;  v.y = __int_as_float(i);
        v.z = -f; v.w = __int_as_float(-1);
        __stcg(reinterpret_cast<float4*>(&g_pack[pr]), v);
    } else {
        __stcg(&g_pack[pr], make_float2( f, __int_as_float(i)));
        __stcg(&g_pack[po], make_float2(-f, __int_as_float(-1)));
    }
}

// ------- kernel 2: single-pass lookback scan + direct ynode scatter --------
// 245 tiles of 4096: every SM gets work (vs 123 tiles before).
__global__ __launch_bounds__(STHREADS) void k_scan(int T)
{
    __shared__ unsigned s_bid;
    __shared__ float    s_excl;
    __shared__ float    s_warp[STHREADS / 32];

    int t = threadIdx.x;
    int lane = t & 31;
    int w = t >> 5;

    if (t == 0) s_bid = atomicAdd((unsigned int*)&g_scan_state[0], 1u);
    __syncthreads();
    int b = (int)s_bid;
    unsigned long long* desc = g_scan_state + 1;

    int base = b * STILE;
    bool full = (base + STILE <= T);

    float e[SIPT];
    int   nd[SIPT];
    if (full) {
        const float4* src = reinterpret_cast<const float4*>(g_pack + base + t * SIPT);
#pragma unroll
        for (int q = 0; q < SIPT / 2; q++) {
            float4 v = __ldcs(src + q);
            e[q*2+0] = v.x;  nd[q*2+0] = __float_as_int(v.y);
            e[q*2+1] = v.z;  nd[q*2+1] = __float_as_int(v.w);
        }
    } else {
#pragma unroll
        for (int j = 0; j < SIPT; j++) {
            int g = base + t * SIPT + j;
            if (g < T) {
                float2 v = g_pack[g];
                e[j] = v.x;
                nd[j] = __float_as_int(v.y);
            } else {
                e[j] = 0.0f;
                nd[j] = -1;
            }
        }
    }

    float run = 0.0f;
#pragma unroll
    for (int j = 0; j < SIPT; j++) { run += e[j]; e[j] = run; }

    float incl = run;
#pragma unroll
    for (int o = 1; o < 32; o <<= 1) {
        float nbr = __shfl_up_sync(0xffffffffu, incl, o);
        if (lane >= o) incl += nbr;
    }
    if (lane == 31) s_warp[w] = incl;
    __syncthreads();
    if (t == 0) {
        float acc = 0.0f;
#pragma unroll
        for (int k = 0; k < STHREADS / 32; k++) { acc += s_warp[k]; s_warp[k] = acc; }
    }
    __syncthreads();
    float thr_excl = incl - run + (w > 0 ? s_warp[w - 1] : 0.0f);
    float block_total = s_warp[STHREADS / 32 - 1];

    if (t == 0) {
        unsigned long long d = (b == 0) ? pack_desc(block_total, FLAG_PRE)
                                        : pack_desc(block_total, FLAG_AGG);
        atomicExch(&desc[b], d);
        if (b == 0) s_excl = 0.0f;
    }

    if (b > 0 && w == 0) {
        float running = 0.0f;
        int tile_idx = b - 1;
        while (true) {
            int idx = tile_idx - lane;
            unsigned f;
            float val;
            if (idx < 0) { f = FLAG_PRE; val = 0.0f; }
            else {
                unsigned long long d;
                do {
                    d = *((volatile unsigned long long*)&desc[idx]);
                    f = (unsigned)(d >> 32);
                } while (f == 0u);
                val = __uint_as_float((unsigned)(d & 0xffffffffull));
            }
            unsigned pmask = __ballot_sync(0xffffffffu, f == FLAG_PRE);
            if (pmask) {
                int fp = __ffs(pmask) - 1;
                float c = (lane <= fp) ? val : 0.0f;
#pragma unroll
                for (int o = 16; o > 0; o >>= 1) c += __shfl_xor_sync(0xffffffffu, c, o);
                running += c;
                break;
            } else {
                float c = val;
#pragma unroll
                for (int o = 16; o > 0; o >>= 1) c += __shfl_xor_sync(0xffffffffu, c, o);
                running += c;
                tile_idx -= 32;
            }
        }
        if (lane == 0) {
            s_excl = running;
            atomicExch(&desc[b], pack_desc(running + block_total, FLAG_PRE));
        }
    }
    __syncthreads();
    float add = s_excl + thr_excl;

#pragma unroll
    for (int j = 0; j < SIPT; j++) {
        int node = nd[j];
        if (node >= 0) __stcg(&g_ynode[node], e[j] + add);
    }
}

// -------- kernel 3: persistent per-pixel gather (exactly-resident grid) ----
__global__ __launch_bounds__(256) void k_gather(const int* __restrict__ nop,
                                                float* __restrict__ out,
                                                int nchunk, int P)
{
    int tid = blockIdx.x * blockDim.x + threadIdx.x;
    int stride = gridDim.x * blockDim.x;

    for (int k = tid; k < nchunk; k += stride) {
        int i = k * 8;
        int4 n0 = *reinterpret_cast<const int4*>(nop + i);
        int4 n1 = *reinterpret_cast<const int4*>(nop + i + 4);
        float4 r0, r1;
        r0.x = __ldg(g_ynode + n0.x);
        r0.y = __ldg(g_ynode + n0.y);
        r0.z = __ldg(g_ynode + n0.z);
        r0.w = __ldg(g_ynode + n0.w);
        r1.x = __ldg(g_ynode + n1.x);
        r1.y = __ldg(g_ynode + n1.y);
        r1.z = __ldg(g_ynode + n1.z);
        r1.w = __ldg(g_ynode + n1.w);
        *reinterpret_cast<float4*>(out + i)     = r0;
        *reinterpret_cast<float4*>(out + i + 4) = r1;
    }
    // Tail pixels (P not divisible by 8)
    for (int j = nchunk * 8 + tid; j < P; j += stride)
        out[j] = g_ynode[nop[j]];
}

// ---------------------------------------------------------------------------
extern "C" void kernel_launch(void* const* d_in, const int* in_sizes, int n_in,
                              void* d_out, int out_size)
{
    const float* weight   = (const float*)d_in[0];
    const float* bias     = (const float*)d_in[1];
    const float* residues = (const float*)d_in[2];
    const float* attrs    = (const float*)d_in[3];
    const int*   tpre     = (const int*)d_in[4];
    const int*   tpost    = (const int*)d_in[5];
    const int*   nop      = (const int*)d_in[6];

    int N = in_sizes[2];
    int P = in_sizes[6];
    int T = 2 * N;
    int nb = (T + STILE - 1) / STILE;     // 245 tiles: all 148 SMs active

    k_filtered<<<(N + 255) / 256, 256>>>(weight, bias, residues, attrs,
                                         tpre, tpost, N, nb + 1);
    k_scan<<<nb, STHREADS>>>(T);

    int nchunk = P / 8;
    k_gather<<<1184, 256>>>(nop, (float*)d_out, nchunk, P);   // 8 blocks/SM
}

// round 14
// speedup vs baseline: 1.0128x; 1.0128x over previous
#include <cuda_runtime.h>
#include <math.h>

// ---------------------------------------------------------------------------
// ConnectedFilterLayerWithImplicitJacobian
//   filtered = residues * sigmoid(attrs2d @ w + b)
//   pack[tpre[i]]  = {+f, i};  pack[tpost[i]] = {-f, -1}   (permutation;
//   aligned leaves -> single 16B store)
//   scan pack.x with decoupled lookback (123 tiles of 8192, 1024 thr);
//   at tpre slots scatter final prefix straight into y_node[node].
//   out[p] = y_node[node_of_pixel[p]]   (gather at L1tex wavefront floor)
// ---------------------------------------------------------------------------

#define TMAX     (1 << 20)          // 2N = 1,000,000 <= 1,048,576
#define NMAX     (1 << 19)          // N = 500,000 <= 524,288
#define STILE    8192
#define STHREADS 1024
#define SIPT     (STILE / STHREADS) // 8 packed elems per thread

__device__ float2 g_pack[TMAX];     // .x = delta value, .y = node id bits
__device__ float  g_ynode[NMAX];
// [0] = ticket counter, [1..] = lookback descriptors (flag<<32 | float bits)
__device__ unsigned long long g_scan_state[256];

#define FLAG_AGG 1u
#define FLAG_PRE 2u

__device__ __forceinline__ unsigned long long pack_desc(float v, unsigned f) {
    return ((unsigned long long)f << 32) | (unsigned long long)__float_as_uint(v);
}

// --------------- kernel 1: filtered + packed scatter (+ state reset) -------
__global__ void k_filtered(const float* __restrict__ weight,
                           const float* __restrict__ bias,
                           const float* __restrict__ residues,
                           const float* __restrict__ attrs,
                           const int*   __restrict__ tpre,
                           const int*   __restrict__ tpost,
                           int n, int nstate)
{
    if (blockIdx.x == 0 && threadIdx.x < nstate)
        g_scan_state[threadIdx.x] = 0ull;

    int i = blockIdx.x * blockDim.x + threadIdx.x;
    if (i >= n) return;

    int pr = tpre[i];
    int po = tpost[i];

    const float4* a = reinterpret_cast<const float4*>(attrs + (size_t)i * 8);
    float4 a0 = a[0];
    float4 a1 = a[1];
    float4 w0 = *reinterpret_cast<const float4*>(weight);
    float4 w1 = *(reinterpret_cast<const float4*>(weight) + 1);

    float logit = a0.x * w0.x + a0.y * w0.y + a0.z * w0.z + a0.w * w0.w
                + a1.x * w1.x + a1.y * w1.y + a1.z * w1.z + a1.w * w1.w
                + bias[0];
    float s = 1.0f / (1.0f + __expf(-logit));
    float f = residues[i] * s;

    // Leaf with aligned tpre: the two 8B entries are one aligned 16B slot.
    if (po == pr + 1 && (pr & 1) == 0) {
        float4 v;
        v.x = f;  v.y = __int_as_float(i);
        v.z = -f; v.w = __int_as_float(-1);
        __stcg(reinterpret_cast<float4*>(&g_pack[pr]), v);
    } else {
        __stcg(&g_pack[pr], make_float2( f, __int_as_float(i)));
        __stcg(&g_pack[po], make_float2(-f, __int_as_float(-1)));
    }
}

// ------- kernel 2: single-pass lookback scan + direct ynode scatter --------
// 123 tiles of 8192, 1024 threads (8 elems/thread): single wave.
__global__ __launch_bounds__(STHREADS) void k_scan(int T)
{
    __shared__ unsigned s_bid;
    __shared__ float    s_excl;
    __shared__ float    s_warp[STHREADS / 32];

    int t = threadIdx.x;
    int lane = t & 31;
    int w = t >> 5;

    if (t == 0) s_bid = atomicAdd((unsigned int*)&g_scan_state[0], 1u);
    __syncthreads();
    int b = (int)s_bid;
    unsigned long long* desc = g_scan_state + 1;

    int base = b * STILE;
    bool full = (base + STILE <= T);

    float e[SIPT];
    int   nd[SIPT];
    if (full) {
        const float4* src = reinterpret_cast<const float4*>(g_pack + base + t * SIPT);
#pragma unroll
        for (int q = 0; q < SIPT / 2; q++) {
            float4 v = __ldcs(src + q);
            e[q*2+0] = v.x;  nd[q*2+0] = __float_as_int(v.y);
            e[q*2+1] = v.z;  nd[q*2+1] = __float_as_int(v.w);
        }
    } else {
#pragma unroll
        for (int j = 0; j < SIPT; j++) {
            int g = base + t * SIPT + j;
            if (g < T) {
                float2 v = g_pack[g];
                e[j] = v.x;
                nd[j] = __float_as_int(v.y);
            } else {
                e[j] = 0.0f;
                nd[j] = -1;
            }
        }
    }

    float run = 0.0f;
#pragma unroll
    for (int j = 0; j < SIPT; j++) { run += e[j]; e[j] = run; }

    float incl = run;
#pragma unroll
    for (int o = 1; o < 32; o <<= 1) {
        float nbr = __shfl_up_sync(0xffffffffu, incl, o);
        if (lane >= o) incl += nbr;
    }
    if (lane == 31) s_warp[w] = incl;
    __syncthreads();
    if (t == 0) {
        float acc = 0.0f;
#pragma unroll
        for (int k = 0; k < STHREADS / 32; k++) { acc += s_warp[k]; s_warp[k] = acc; }
    }
    __syncthreads();
    float thr_excl = incl - run + (w > 0 ? s_warp[w - 1] : 0.0f);
    float block_total = s_warp[STHREADS / 32 - 1];

    if (t == 0) {
        unsigned long long d = (b == 0) ? pack_desc(block_total, FLAG_PRE)
                                        : pack_desc(block_total, FLAG_AGG);
        atomicExch(&desc[b], d);
        if (b == 0) s_excl = 0.0f;
    }

    if (b > 0 && w == 0) {
        float running = 0.0f;
        int tile_idx = b - 1;
        while (true) {
            int idx = tile_idx - lane;
            unsigned f;
            float val;
            if (idx < 0) { f = FLAG_PRE; val = 0.0f; }
            else {
                unsigned long long d;
                do {
                    d = *((volatile unsigned long long*)&desc[idx]);
                    f = (unsigned)(d >> 32);
                } while (f == 0u);
                val = __uint_as_float((unsigned)(d & 0xffffffffull));
            }
            unsigned pmask = __ballot_sync(0xffffffffu, f == FLAG_PRE);
            if (pmask) {
                int fp = __ffs(pmask) - 1;
                float c = (lane <= fp) ? val : 0.0f;
#pragma unroll
                for (int o = 16; o > 0; o >>= 1) c += __shfl_xor_sync(0xffffffffu, c, o);
                running += c;
                break;
            } else {
                float c = val;
#pragma unroll
                for (int o = 16; o > 0; o >>= 1) c += __shfl_xor_sync(0xffffffffu, c, o);
                running += c;
                tile_idx -= 32;
            }
        }
        if (lane == 0) {
            s_excl = running;
            atomicExch(&desc[b], pack_desc(running + block_total, FLAG_PRE));
        }
    }
    __syncthreads();
    float add = s_excl + thr_excl;

#pragma unroll
    for (int j = 0; j < SIPT; j++) {
        int node = nd[j];
        if (node >= 0) __stcg(&g_ynode[node], e[j] + add);
    }
}

// --------------- per-pixel gather (R11 exact config: best measured) ---------
__global__ __launch_bounds__(512) void k_gather(const int* __restrict__ nop,
                                                float* __restrict__ out,
                                                int P)
{
    int i = (blockIdx.x * blockDim.x + threadIdx.x) * 8;
    if (i + 7 < P) {
        int4 n0 = *reinterpret_cast<const int4*>(nop + i);
        int4 n1 = *reinterpret_cast<const int4*>(nop + i + 4);
        float4 r0, r1;
        r0.x = __ldg(g_ynode + n0.x);
        r0.y = __ldg(g_ynode + n0.y);
        r0.z = __ldg(g_ynode + n0.z);
        r0.w = __ldg(g_ynode + n0.w);
        r1.x = __ldg(g_ynode + n1.x);
        r1.y = __ldg(g_ynode + n1.y);
        r1.z = __ldg(g_ynode + n1.z);
        r1.w = __ldg(g_ynode + n1.w);
        *reinterpret_cast<float4*>(out + i)     = r0;
        *reinterpret_cast<float4*>(out + i + 4) = r1;
    } else {
        for (int j = i; j < P; j++) out[j] = g_ynode[nop[j]];
    }
}

// ---------------------------------------------------------------------------
extern "C" void kernel_launch(void* const* d_in, const int* in_sizes, int n_in,
                              void* d_out, int out_size)
{
    const float* weight   = (const float*)d_in[0];
    const float* bias     = (const float*)d_in[1];
    const float* residues = (const float*)d_in[2];
    const float* attrs    = (const float*)d_in[3];
    const int*   tpre     = (const int*)d_in[4];
    const int*   tpost    = (const int*)d_in[5];
    const int*   nop      = (const int*)d_in[6];

    int N = in_sizes[2];
    int P = in_sizes[6];
    int T = 2 * N;
    int nb = (T + STILE - 1) / STILE;     // 123 tiles: single wave

    k_filtered<<<(N + 255) / 256, 256>>>(weight, bias, residues, attrs,
                                         tpre, tpost, N, nb + 1);
    k_scan<<<nb, STHREADS>>>(T);

    int gt = (P + 7) / 8;
    k_gather<<<(gt + 511) / 512, 512>>>(nop, (float*)d_out, P);
}

// round 15
// speedup vs baseline: 1.0151x; 1.0022x over previous
#include <cuda_runtime.h>
#include <math.h>

// ---------------------------------------------------------------------------
// ConnectedFilterLayerWithImplicitJacobian
//   filtered = residues * sigmoid(attrs2d @ w + b)
//   pack[tpre[i]]  = {+f, i};  pack[tpost[i]] = {-f, -1}   (permutation;
//   aligned leaves -> single 16B store)
//   scan pack.x with decoupled lookback (123 tiles of 8192, 1024 thr);
//   at tpre slots scatter final prefix straight into y_node[node].
//   out[p] = y_node[node_of_pixel[p]]   (gather at L1tex wavefront floor)
// ---------------------------------------------------------------------------

#define TMAX     (1 << 20)          // 2N = 1,000,000 <= 1,048,576
#define NMAX     (1 << 19)          // N = 500,000 <= 524,288
#define STILE    8192
#define STHREADS 1024
#define SIPT     (STILE / STHREADS) // 8 packed elems per thread
#define FBLOCKS  1184               // 8 blocks/SM * 148 SMs: exactly resident

__device__ float2 g_pack[TMAX];     // .x = delta value, .y = node id bits
__device__ float  g_ynode[NMAX];
// [0] = ticket counter, [1..] = lookback descriptors (flag<<32 | float bits)
__device__ unsigned long long g_scan_state[256];

#define FLAG_AGG 1u
#define FLAG_PRE 2u

__device__ __forceinline__ unsigned long long pack_desc(float v, unsigned f) {
    return ((unsigned long long)f << 32) | (unsigned long long)__float_as_uint(v);
}

// ------- kernel 1: filtered + packed scatter (persistent, 1 wave) ----------
__global__ __launch_bounds__(256) void k_filtered(
    const float* __restrict__ weight,
    const float* __restrict__ bias,
    const float* __restrict__ residues,
    const float* __restrict__ attrs,
    const int*   __restrict__ tpre,
    const int*   __restrict__ tpost,
    int n, int nstate)
{
    if (blockIdx.x == 0 && threadIdx.x < nstate)
        g_scan_state[threadIdx.x] = 0ull;

    float4 w0 = *reinterpret_cast<const float4*>(weight);
    float4 w1 = *(reinterpret_cast<const float4*>(weight) + 1);
    float  b0 = bias[0];

    int tid    = blockIdx.x * blockDim.x + threadIdx.x;
    int stride = gridDim.x * blockDim.x;

    for (int i = tid; i < n; i += stride) {
        int pr = tpre[i];
        int po = tpost[i];

        const float4* a = reinterpret_cast<const float4*>(attrs + (size_t)i * 8);
        float4 a0 = a[0];
        float4 a1 = a[1];

        float logit = a0.x * w0.x + a0.y * w0.y + a0.z * w0.z + a0.w * w0.w
                    + a1.x * w1.x + a1.y * w1.y + a1.z * w1.z + a1.w * w1.w
                    + b0;
        float f = residues[i] * (1.0f / (1.0f + __expf(-logit)));

        // Leaf with aligned tpre: the two 8B entries are one aligned 16B slot.
        if (po == pr + 1 && (pr & 1) == 0) {
            float4 v;
            v.x = f;  v.y = __int_as_float(i);
            v.z = -f; v.w = __int_as_float(-1);
            __stcg(reinterpret_cast<float4*>(&g_pack[pr]), v);
        } else {
            __stcg(&g_pack[pr], make_float2( f, __int_as_float(i)));
            __stcg(&g_pack[po], make_float2(-f, __int_as_float(-1)));
        }
    }
}

// ------- kernel 2: single-pass lookback scan + direct ynode scatter --------
// 123 tiles of 8192, 1024 threads (8 elems/thread): single wave.
__global__ __launch_bounds__(STHREADS) void k_scan(int T)
{
    __shared__ unsigned s_bid;
    __shared__ float    s_excl;
    __shared__ float    s_warp[STHREADS / 32];

    int t = threadIdx.x;
    int lane = t & 31;
    int w = t >> 5;

    if (t == 0) s_bid = atomicAdd((unsigned int*)&g_scan_state[0], 1u);
    __syncthreads();
    int b = (int)s_bid;
    unsigned long long* desc = g_scan_state + 1;

    int base = b * STILE;
    bool full = (base + STILE <= T);

    float e[SIPT];
    int   nd[SIPT];
    if (full) {
        const float4* src = reinterpret_cast<const float4*>(g_pack + base + t * SIPT);
#pragma unroll
        for (int q = 0; q < SIPT / 2; q++) {
            float4 v = __ldcs(src + q);
            e[q*2+0] = v.x;  nd[q*2+0] = __float_as_int(v.y);
            e[q*2+1] = v.z;  nd[q*2+1] = __float_as_int(v.w);
        }
    } else {
#pragma unroll
        for (int j = 0; j < SIPT; j++) {
            int g = base + t * SIPT + j;
            if (g < T) {
                float2 v = g_pack[g];
                e[j] = v.x;
                nd[j] = __float_as_int(v.y);
            } else {
                e[j] = 0.0f;
                nd[j] = -1;
            }
        }
    }

    float run = 0.0f;
#pragma unroll
    for (int j = 0; j < SIPT; j++) { run += e[j]; e[j] = run; }

    float incl = run;
#pragma unroll
    for (int o = 1; o < 32; o <<= 1) {
        float nbr = __shfl_up_sync(0xffffffffu, incl, o);
        if (lane >= o) incl += nbr;
    }
    if (lane == 31) s_warp[w] = incl;
    __syncthreads();
    if (t == 0) {
        float acc = 0.0f;
#pragma unroll
        for (int k = 0; k < STHREADS / 32; k++) { acc += s_warp[k]; s_warp[k] = acc; }
    }
    __syncthreads();
    float thr_excl = incl - run + (w > 0 ? s_warp[w - 1] : 0.0f);
    float block_total = s_warp[STHREADS / 32 - 1];

    if (t == 0) {
        unsigned long long d = (b == 0) ? pack_desc(block_total, FLAG_PRE)
                                        : pack_desc(block_total, FLAG_AGG);
        atomicExch(&desc[b], d);
        if (b == 0) s_excl = 0.0f;
    }

    if (b > 0 && w == 0) {
        float running = 0.0f;
        int tile_idx = b - 1;
        while (true) {
            int idx = tile_idx - lane;
            unsigned f;
            float val;
            if (idx < 0) { f = FLAG_PRE; val = 0.0f; }
            else {
                unsigned long long d;
                do {
                    d = *((volatile unsigned long long*)&desc[idx]);
                    f = (unsigned)(d >> 32);
                } while (f == 0u);
                val = __uint_as_float((unsigned)(d & 0xffffffffull));
            }
            unsigned pmask = __ballot_sync(0xffffffffu, f == FLAG_PRE);
            if (pmask) {
                int fp = __ffs(pmask) - 1;
                float c = (lane <= fp) ? val : 0.0f;
#pragma unroll
                for (int o = 16; o > 0; o >>= 1) c += __shfl_xor_sync(0xffffffffu, c, o);
                running += c;
                break;
            } else {
                float c = val;
#pragma unroll
                for (int o = 16; o > 0; o >>= 1) c += __shfl_xor_sync(0xffffffffu, c, o);
                running += c;
                tile_idx -= 32;
            }
        }
        if (lane == 0) {
            s_excl = running;
            atomicExch(&desc[b], pack_desc(running + block_total, FLAG_PRE));
        }
    }
    __syncthreads();
    float add = s_excl + thr_excl;

#pragma unroll
    for (int j = 0; j < SIPT; j++) {
        int node = nd[j];
        if (node >= 0) __stcg(&g_ynode[node], e[j] + add);
    }
}

// --------------- per-pixel gather (R13 exact config: best measured) ---------
__global__ __launch_bounds__(512) void k_gather(const int* __restrict__ nop,
                                                float* __restrict__ out,
                                                int P)
{
    int i = (blockIdx.x * blockDim.x + threadIdx.x) * 8;
    if (i + 7 < P) {
        int4 n0 = *reinterpret_cast<const int4*>(nop + i);
        int4 n1 = *reinterpret_cast<const int4*>(nop + i + 4);
        float4 r0, r1;
        r0.x = __ldg(g_ynode + n0.x);
        r0.y = __ldg(g_ynode + n0.y);
        r0.z = __ldg(g_ynode + n0.z);
        r0.w = __ldg(g_ynode + n0.w);
        r1.x = __ldg(g_ynode + n1.x);
        r1.y = __ldg(g_ynode + n1.y);
        r1.z = __ldg(g_ynode + n1.z);
        r1.w = __ldg(g_ynode + n1.w);
        *reinterpret_cast<float4*>(out + i)     = r0;
        *reinterpret_cast<float4*>(out + i + 4) = r1;
    } else {
        for (int j = i; j < P; j++) out[j] = g_ynode[nop[j]];
    }
}

// ---------------------------------------------------------------------------
extern "C" void kernel_launch(void* const* d_in, const int* in_sizes, int n_in,
                              void* d_out, int out_size)
{
    const float* weight   = (const float*)d_in[0];
    const float* bias     = (const float*)d_in[1];
    const float* residues = (const float*)d_in[2];
    const float* attrs    = (const float*)d_in[3];
    const int*   tpre     = (const int*)d_in[4];
    const int*   tpost    = (const int*)d_in[5];
    const int*   nop      = (const int*)d_in[6];

    int N = in_sizes[2];
    int P = in_sizes[6];
    int T = 2 * N;
    int nb = (T + STILE - 1) / STILE;     // 123 tiles: single wave

    k_filtered<<<FBLOCKS, 256>>>(weight, bias, residues, attrs,
                                 tpre, tpost, N, nb + 1);
    k_scan<<<nb, STHREADS>>>(T);

    int gt = (P + 7) / 8;
    k_gather<<<(gt + 511) / 512, 512>>>(nop, (float*)d_out, P);
}

// round 16
// speedup vs baseline: 1.0353x; 1.0200x over previous
#include <cuda_runtime.h>
#include <math.h>

// ---------------------------------------------------------------------------
// ConnectedFilterLayerWithImplicitJacobian
//   filtered = residues * sigmoid(attrs2d @ w + b)
//   pack[tpre[i]]  = {+f, i};  pack[tpost[i]] = {-f, -1}   (permutation;
//   aligned leaves -> single 16B store)
//   scan pack.x with decoupled lookback (123 tiles of 8192, 1024 thr);
//   at tpre slots scatter final prefix straight into y_node[node].
//   out[p] = y_node[node_of_pixel[p]]   (gather at L1tex wavefront floor)
// ---------------------------------------------------------------------------

#define TMAX     (1 << 20)          // 2N = 1,000,000 <= 1,048,576
#define NMAX     (1 << 19)          // N = 500,000 <= 524,288
#define STILE    8192
#define STHREADS 1024
#define SIPT     (STILE / STHREADS) // 8 packed elems per thread
#define FBLOCKS  1184               // 8 blocks/SM * 148 SMs: exactly resident

__device__ float2 g_pack[TMAX];     // .x = delta value, .y = node id bits
__device__ float  g_ynode[NMAX];
// [0] = ticket counter, [1..] = lookback descriptors (flag<<32 | float bits)
__device__ unsigned long long g_scan_state[256];

#define FLAG_AGG 1u
#define FLAG_PRE 2u

__device__ __forceinline__ unsigned long long pack_desc(float v, unsigned f) {
    return ((unsigned long long)f << 32) | (unsigned long long)__float_as_uint(v);
}

// ------- kernel 1: filtered + packed scatter (persistent, 1 wave) ----------
__global__ __launch_bounds__(256) void k_filtered(
    const float* __restrict__ weight,
    const float* __restrict__ bias,
    const float* __restrict__ residues,
    const float* __restrict__ attrs,
    const int*   __restrict__ tpre,
    const int*   __restrict__ tpost,
    int n, int nstate)
{
    if (blockIdx.x == 0 && threadIdx.x < nstate)
        g_scan_state[threadIdx.x] = 0ull;

    float4 w0 = *reinterpret_cast<const float4*>(weight);
    float4 w1 = *(reinterpret_cast<const float4*>(weight) + 1);
    float  b0 = bias[0];

    int tid    = blockIdx.x * blockDim.x + threadIdx.x;
    int stride = gridDim.x * blockDim.x;

    for (int i = tid; i < n; i += stride) {
        int pr = tpre[i];
        int po = tpost[i];

        const float4* a = reinterpret_cast<const float4*>(attrs + (size_t)i * 8);
        float4 a0 = a[0];
        float4 a1 = a[1];

        float logit = a0.x * w0.x + a0.y * w0.y + a0.z * w0.z + a0.w * w0.w
                    + a1.x * w1.x + a1.y * w1.y + a1.z * w1.z + a1.w * w1.w
                    + b0;
        float f = residues[i] * (1.0f / (1.0f + __expf(-logit)));

        // Leaf with aligned tpre: the two 8B entries are one aligned 16B slot.
        if (po == pr + 1 && (pr & 1) == 0) {
            float4 v;
            v.x = f;  v.y = __int_as_float(i);
            v.z = -f; v.w = __int_as_float(-1);
            __stcg(reinterpret_cast<float4*>(&g_pack[pr]), v);
        } else {
            __stcg(&g_pack[pr], make_float2( f, __int_as_float(i)));
            __stcg(&g_pack[po], make_float2(-f, __int_as_float(-1)));
        }
    }
}

// ------- kernel 2: single-pass lookback scan + direct ynode scatter --------
// 123 tiles of 8192, 1024 threads (8 elems/thread): single wave.
__global__ __launch_bounds__(STHREADS) void k_scan(int T)
{
    __shared__ unsigned s_bid;
    __shared__ float    s_excl;
    __shared__ float    s_warp[STHREADS / 32];

    int t = threadIdx.x;
    int lane = t & 31;
    int w = t >> 5;

    if (t == 0) s_bid = atomicAdd((unsigned int*)&g_scan_state[0], 1u);
    __syncthreads();
    int b = (int)s_bid;
    unsigned long long* desc = g_scan_state + 1;

    int base = b * STILE;
    bool full = (base + STILE <= T);

    float e[SIPT];
    int   nd[SIPT];
    if (full) {
        const float4* src = reinterpret_cast<const float4*>(g_pack + base + t * SIPT);
#pragma unroll
        for (int q = 0; q < SIPT / 2; q++) {
            float4 v = __ldcs(src + q);
            e[q*2+0] = v.x;  nd[q*2+0] = __float_as_int(v.y);
            e[q*2+1] = v.z;  nd[q*2+1] = __float_as_int(v.w);
        }
    } else {
#pragma unroll
        for (int j = 0; j < SIPT; j++) {
            int g = base + t * SIPT + j;
            if (g < T) {
                float2 v = g_pack[g];
                e[j] = v.x;
                nd[j] = __float_as_int(v.y);
            } else {
                e[j] = 0.0f;
                nd[j] = -1;
            }
        }
    }

    float run = 0.0f;
#pragma unroll
    for (int j = 0; j < SIPT; j++) { run += e[j]; e[j] = run; }

    float incl = run;
#pragma unroll
    for (int o = 1; o < 32; o <<= 1) {
        float nbr = __shfl_up_sync(0xffffffffu, incl, o);
        if (lane >= o) incl += nbr;
    }
    if (lane == 31) s_warp[w] = incl;
    __syncthreads();
    if (t == 0) {
        float acc = 0.0f;
#pragma unroll
        for (int k = 0; k < STHREADS / 32; k++) { acc += s_warp[k]; s_warp[k] = acc; }
    }
    __syncthreads();
    float thr_excl = incl - run + (w > 0 ? s_warp[w - 1] : 0.0f);
    float block_total = s_warp[STHREADS / 32 - 1];

    if (t == 0) {
        unsigned long long d = (b == 0) ? pack_desc(block_total, FLAG_PRE)
                                        : pack_desc(block_total, FLAG_AGG);
        atomicExch(&desc[b], d);
        if (b == 0) s_excl = 0.0f;
    }

    if (b > 0 && w == 0) {
        float running = 0.0f;
        int tile_idx = b - 1;
        while (true) {
            int idx = tile_idx - lane;
            unsigned f;
            float val;
            if (idx < 0) { f = FLAG_PRE; val = 0.0f; }
            else {
                unsigned long long d;
                do {
                    d = *((volatile unsigned long long*)&desc[idx]);
                    f = (unsigned)(d >> 32);
                } while (f == 0u);
                val = __uint_as_float((unsigned)(d & 0xffffffffull));
            }
            unsigned pmask = __ballot_sync(0xffffffffu, f == FLAG_PRE);
            if (pmask) {
                int fp = __ffs(pmask) - 1;
                float c = (lane <= fp) ? val : 0.0f;
#pragma unroll
                for (int o = 16; o > 0; o >>= 1) c += __shfl_xor_sync(0xffffffffu, c, o);
                running += c;
                break;
            } else {
                float c = val;
#pragma unroll
                for (int o = 16; o > 0; o >>= 1) c += __shfl_xor_sync(0xffffffffu, c, o);
                running += c;
                tile_idx -= 32;
            }
        }
        if (lane == 0) {
            s_excl = running;
            atomicExch(&desc[b], pack_desc(running + block_total, FLAG_PRE));
        }
    }
    __syncthreads();
    float add = s_excl + thr_excl;

#pragma unroll
    for (int j = 0; j < SIPT; j++) {
        int node = nd[j];
        if (node >= 0) __stcg(&g_ynode[node], e[j] + add);
    }
}

// --------------- per-pixel gather (R2 exact config: best measured 40.8us) ---
__global__ __launch_bounds__(256) void k_gather(const int* __restrict__ nop,
                                                float* __restrict__ out,
                                                int P)
{
    int i = (blockIdx.x * blockDim.x + threadIdx.x) * 8;
    if (i + 7 < P) {
        int4 n0 = *reinterpret_cast<const int4*>(nop + i);
        int4 n1 = *reinterpret_cast<const int4*>(nop + i + 4);
        float4 r0, r1;
        r0.x = g_ynode[n0.x];
        r0.y = g_ynode[n0.y];
        r0.z = g_ynode[n0.z];
        r0.w = g_ynode[n0.w];
        r1.x = g_ynode[n1.x];
        r1.y = g_ynode[n1.y];
        r1.z = g_ynode[n1.z];
        r1.w = g_ynode[n1.w];
        *reinterpret_cast<float4*>(out + i)     = r0;
        *reinterpret_cast<float4*>(out + i + 4) = r1;
    } else {
        for (int j = i; j < P; j++) out[j] = g_ynode[nop[j]];
    }
}

// ---------------------------------------------------------------------------
extern "C" void kernel_launch(void* const* d_in, const int* in_sizes, int n_in,
                              void* d_out, int out_size)
{
    const float* weight   = (const float*)d_in[0];
    const float* bias     = (const float*)d_in[1];
    const float* residues = (const float*)d_in[2];
    const float* attrs    = (const float*)d_in[3];
    const int*   tpre     = (const int*)d_in[4];
    const int*   tpost    = (const int*)d_in[5];
    const int*   nop      = (const int*)d_in[6];

    int N = in_sizes[2];
    int P = in_sizes[6];
    int T = 2 * N;
    int nb = (T + STILE - 1) / STILE;     // 123 tiles: single wave

    k_filtered<<<FBLOCKS, 256>>>(weight, bias, residues, attrs,
                                 tpre, tpost, N, nb + 1);
    k_scan<<<nb, STHREADS>>>(T);

    int gt = (P + 7) / 8;
    k_gather<<<(gt + 255) / 256, 256>>>(nop, (float*)d_out, P);
}

// round 17
// speedup vs baseline: 1.1040x; 1.0663x over previous
#include <cuda_runtime.h>
#include <math.h>

// ---------------------------------------------------------------------------
// ConnectedFilterLayerWithImplicitJacobian
//   filtered = residues * sigmoid(attrs2d @ w + b)
//   pack[tpre[i]]  = {+f, i};  pack[tpost[i]] = {-f, -1}   (permutation;
//   aligned leaves -> single 16B store)
//   scan pack.x with decoupled lookback (123 tiles of 8192, 1024 thr);
//   at tpre slots scatter final prefix straight into y_node[node].
//   out[p] = y_node[node_of_pixel[p]]   (gather at L1tex wavefront floor)
// ---------------------------------------------------------------------------

#define TMAX     (1 << 20)          // 2N = 1,000,000 <= 1,048,576
#define NMAX     (1 << 19)          // N = 500,000 <= 524,288
#define STILE    8192
#define STHREADS 1024
#define SIPT     (STILE / STHREADS) // 8 packed elems per thread
#define FBLOCKS  1184               // 8 blocks/SM * 148 SMs: exactly resident

__device__ float2 g_pack[TMAX];     // .x = delta value, .y = node id bits
__device__ float  g_ynode[NMAX];
// [0] = ticket counter, [1..] = lookback descriptors (flag<<32 | float bits)
__device__ unsigned long long g_scan_state[256];

#define FLAG_AGG 1u
#define FLAG_PRE 2u

__device__ __forceinline__ unsigned long long pack_desc(float v, unsigned f) {
    return ((unsigned long long)f << 32) | (unsigned long long)__float_as_uint(v);
}

// ------- kernel 1: filtered + packed scatter (persistent, 1 wave) ----------
__global__ __launch_bounds__(256) void k_filtered(
    const float* __restrict__ weight,
    const float* __restrict__ bias,
    const float* __restrict__ residues,
    const float* __restrict__ attrs,
    const int*   __restrict__ tpre,
    const int*   __restrict__ tpost,
    int n, int nstate)
{
    if (blockIdx.x == 0 && threadIdx.x < nstate)
        g_scan_state[threadIdx.x] = 0ull;

    float4 w0 = *reinterpret_cast<const float4*>(weight);
    float4 w1 = *(reinterpret_cast<const float4*>(weight) + 1);
    float  b0 = bias[0];

    int tid    = blockIdx.x * blockDim.x + threadIdx.x;
    int stride = gridDim.x * blockDim.x;

    for (int i = tid; i < n; i += stride) {
        int pr = tpre[i];
        int po = tpost[i];

        const float4* a = reinterpret_cast<const float4*>(attrs + (size_t)i * 8);
        float4 a0 = a[0];
        float4 a1 = a[1];

        float logit = a0.x * w0.x + a0.y * w0.y + a0.z * w0.z + a0.w * w0.w
                    + a1.x * w1.x + a1.y * w1.y + a1.z * w1.z + a1.w * w1.w
                    + b0;
        float f = residues[i] * (1.0f / (1.0f + __expf(-logit)));

        // Leaf with aligned tpre: the two 8B entries are one aligned 16B slot.
        if (po == pr + 1 && (pr & 1) == 0) {
            float4 v;
            v.x = f;  v.y = __int_as_float(i);
            v.z = -f; v.w = __int_as_float(-1);
            __stcg(reinterpret_cast<float4*>(&g_pack[pr]), v);
        } else {
            __stcg(&g_pack[pr], make_float2( f, __int_as_float(i)));
            __stcg(&g_pack[po], make_float2(-f, __int_as_float(-1)));
        }
    }
}

// ------- kernel 2: single-pass lookback scan + direct ynode scatter --------
// 123 tiles of 8192, 1024 threads (8 elems/thread): single wave.
__global__ __launch_bounds__(STHREADS) void k_scan(int T)
{
    __shared__ unsigned s_bid;
    __shared__ float    s_excl;
    __shared__ float    s_warp[STHREADS / 32];

    int t = threadIdx.x;
    int lane = t & 31;
    int w = t >> 5;

    if (t == 0) s_bid = atomicAdd((unsigned int*)&g_scan_state[0], 1u);
    __syncthreads();
    int b = (int)s_bid;
    unsigned long long* desc = g_scan_state + 1;

    int base = b * STILE;
    bool full = (base + STILE <= T);

    float e[SIPT];
    int   nd[SIPT];
    if (full) {
        const float4* src = reinterpret_cast<const float4*>(g_pack + base + t * SIPT);
#pragma unroll
        for (int q = 0; q < SIPT / 2; q++) {
            float4 v = __ldcs(src + q);
            e[q*2+0] = v.x;  nd[q*2+0] = __float_as_int(v.y);
            e[q*2+1] = v.z;  nd[q*2+1] = __float_as_int(v.w);
        }
    } else {
#pragma unroll
        for (int j = 0; j < SIPT; j++) {
            int g = base + t * SIPT + j;
            if (g < T) {
                float2 v = g_pack[g];
                e[j] = v.x;
                nd[j] = __float_as_int(v.y);
            } else {
                e[j] = 0.0f;
                nd[j] = -1;
            }
        }
    }

    float run = 0.0f;
#pragma unroll
    for (int j = 0; j < SIPT; j++) { run += e[j]; e[j] = run; }

    float incl = run;
#pragma unroll
    for (int o = 1; o < 32; o <<= 1) {
        float nbr = __shfl_up_sync(0xffffffffu, incl, o);
        if (lane >= o) incl += nbr;
    }
    if (lane == 31) s_warp[w] = incl;
    __syncthreads();
    if (t == 0) {
        float acc = 0.0f;
#pragma unroll
        for (int k = 0; k < STHREADS / 32; k++) { acc += s_warp[k]; s_warp[k] = acc; }
    }
    __syncthreads();
    float thr_excl = incl - run + (w > 0 ? s_warp[w - 1] : 0.0f);
    float block_total = s_warp[STHREADS / 32 - 1];

    if (t == 0) {
        unsigned long long d = (b == 0) ? pack_desc(block_total, FLAG_PRE)
                                        : pack_desc(block_total, FLAG_AGG);
        atomicExch(&desc[b], d);
        if (b == 0) s_excl = 0.0f;
    }

    if (b > 0 && w == 0) {
        float running = 0.0f;
        int tile_idx = b - 1;
        while (true) {
            int idx = tile_idx - lane;
            unsigned f;
            float val;
            if (idx < 0) { f = FLAG_PRE; val = 0.0f; }
            else {
                unsigned long long d;
                do {
                    d = *((volatile unsigned long long*)&desc[idx]);
                    f = (unsigned)(d >> 32);
                } while (f == 0u);
                val = __uint_as_float((unsigned)(d & 0xffffffffull));
            }
            unsigned pmask = __ballot_sync(0xffffffffu, f == FLAG_PRE);
            if (pmask) {
                int fp = __ffs(pmask) - 1;
                float c = (lane <= fp) ? val : 0.0f;
#pragma unroll
                for (int o = 16; o > 0; o >>= 1) c += __shfl_xor_sync(0xffffffffu, c, o);
                running += c;
                break;
            } else {
                float c = val;
#pragma unroll
                for (int o = 16; o > 0; o >>= 1) c += __shfl_xor_sync(0xffffffffu, c, o);
                running += c;
                tile_idx -= 32;
            }
        }
        if (lane == 0) {
            s_excl = running;
            atomicExch(&desc[b], pack_desc(running + block_total, FLAG_PRE));
        }
    }
    __syncthreads();
    float add = s_excl + thr_excl;

#pragma unroll
    for (int j = 0; j < SIPT; j++) {
        int node = nd[j];
        if (node >= 0) __stcg(&g_ynode[node], e[j] + add);
    }
}

// --------------- per-pixel gather: 4 px/thread (finer granularity) ----------
__global__ __launch_bounds__(256) void k_gather(const int* __restrict__ nop,
                                                float* __restrict__ out,
                                                int P)
{
    int i = (blockIdx.x * blockDim.x + threadIdx.x) * 4;
    if (i + 3 < P) {
        int4 n0 = *reinterpret_cast<const int4*>(nop + i);
        float4 r0;
        r0.x = g_ynode[n0.x];
        r0.y = g_ynode[n0.y];
        r0.z = g_ynode[n0.z];
        r0.w = g_ynode[n0.w];
        *reinterpret_cast<float4*>(out + i) = r0;
    } else {
        for (int j = i; j < P; j++) out[j] = g_ynode[nop[j]];
    }
}

// ---------------------------------------------------------------------------
extern "C" void kernel_launch(void* const* d_in, const int* in_sizes, int n_in,
                              void* d_out, int out_size)
{
    const float* weight   = (const float*)d_in[0];
    const float* bias     = (const float*)d_in[1];
    const float* residues = (const float*)d_in[2];
    const float* attrs    = (const float*)d_in[3];
    const int*   tpre     = (const int*)d_in[4];
    const int*   tpost    = (const int*)d_in[5];
    const int*   nop      = (const int*)d_in[6];

    int N = in_sizes[2];
    int P = in_sizes[6];
    int T = 2 * N;
    int nb = (T + STILE - 1) / STILE;     // 123 tiles: single wave

    k_filtered<<<FBLOCKS, 256>>>(weight, bias, residues, attrs,
                                 tpre, tpost, N, nb + 1);
    k_scan<<<nb, STHREADS>>>(T);

    int gt = (P + 3) / 4;
    k_gather<<<(gt + 255) / 256, 256>>>(nop, (float*)d_out, P);
}